// round 4
// baseline (speedup 1.0000x reference)
// Fused gather+concat -> Linear(256,1024) -> exact GELU -> Linear(1024,2)
// sm_100 (non-'a') target: legacy mma.sync m16n8k8 tf32, cp.async double buffer.
// 2048 CTAs x (M=128, K=256), N streamed in 32-col chunks. 8 warps, 4m x 2n,
// warp tile 32x16. W1 pre-shuffled into mma fragment order in gmem (prep
// kernel); A gathered into fragment order in smem. Epilogue fused per chunk.
// R4 fix: cvt.rna.tf32.f32 needs a .b32 destination (was "=f", now "=r").

#include <cuda_runtime.h>
#include <cstdint>

#define NTHREADS   256
#define TILE_M     128
#define NCHUNKS    32          // 1024 / 32
#define KSTEPS     32          // 256 / 8

// smem layout (bytes)
#define OFF_IDX    0           // 256 ints
#define OFF_CMB    1024        // 128 float2
#define OFF_B1     2048        // 1024 f32
#define OFF_W2     6144        // 1024 float2
#define OFF_A      14336       // A fragments: 32 ksteps x 8 mtiles x 32 lanes x 16B
#define OFF_B      145408      // 2 x 32KB B chunk buffers
#define SMEM_BYTES 210944

// ---------------- helpers ----------------
__device__ __forceinline__ uint32_t smem_u32(const void* p) {
    uint32_t a;
    asm("{ .reg .u64 t; cvta.to.shared.u64 t, %1; cvt.u32.u64 %0, t; }"
        : "=r"(a) : "l"(p));
    return a;
}

#define CP_ASYNC16(dst, src) \
    asm volatile("cp.async.cg.shared.global [%0], [%1], 16;" :: "r"(dst), "l"(src))
#define CP_COMMIT() asm volatile("cp.async.commit_group;" ::: "memory")
#define CP_WAIT(n)  asm volatile("cp.async.wait_group %0;" :: "n"(n) : "memory")

// tf32 round-to-nearest; destination of cvt.*.tf32 must be a b32 register
__device__ __forceinline__ float ftf32(float x) {
    uint32_t r;
    asm("cvt.rna.tf32.f32 %0, %1;" : "=r"(r) : "f"(x));
    return __uint_as_float(r);
}

__device__ __forceinline__ void mma_tf32(float& c0, float& c1, float& c2, float& c3,
                                         uint32_t a0, uint32_t a1, uint32_t a2, uint32_t a3,
                                         uint32_t b0, uint32_t b1) {
    asm volatile("mma.sync.aligned.m16n8k8.row.col.f32.tf32.tf32.f32 "
                 "{%0,%1,%2,%3}, {%4,%5,%6,%7}, {%8,%9}, {%0,%1,%2,%3};"
                 : "+f"(c0), "+f"(c1), "+f"(c2), "+f"(c3)
                 : "r"(a0), "r"(a1), "r"(a2), "r"(a3), "r"(b0), "r"(b1));
}

// GELU with exact erf via A&S 7.1.26 (|eps| < 1.5e-7)
__device__ __forceinline__ float gelu_exact(float x) {
    float z = fabsf(x) * 0.70710678118654752f;
    float den = fmaf(z, 0.3275911f, 1.0f);
    float t; asm("rcp.approx.f32 %0, %1;" : "=f"(t) : "f"(den));
    float e = __expf(-z * z);
    float p = t * fmaf(t, fmaf(t, fmaf(t, fmaf(t, 0.5307027145f, -0.7265760135f),
                                       0.7107068705f), -0.142248368f), 0.127414796f);
    float q = p * e;                        // 0.5*(1-erf(z))
    float sc = copysignf(1.0f, x);
    float phi = fmaf(sc, 0.5f - q, 0.5f);   // Phi(x)
    return x * phi;
}

// ---------------- W1 -> fragment-order gmem (prep) ----------------
// Layout: [nc(32)][ks(32)][t(4)][lane(32)] float2{b0,b1}
//   b0 = W1[ks*8 + lane%4    ][nc*32 + t*8 + lane/4]
//   b1 = W1[ks*8 + lane%4 + 4][nc*32 + t*8 + lane/4]
__device__ __align__(16) float2 g_bfrag[131072];

__global__ void prep_bfrag_kernel(const float* __restrict__ W1) {
    int idx = blockIdx.x * blockDim.x + threadIdx.x;   // 0 .. 131071
    int lane = idx & 31;
    int t    = (idx >> 5) & 3;
    int ks   = (idx >> 7) & 31;
    int nc   = idx >> 12;
    int n = nc * 32 + t * 8 + (lane >> 2);
    int k = ks * 8 + (lane & 3);
    float2 v;
    v.x = ftf32(W1[k * 1024 + n]);
    v.y = ftf32(W1[(k + 4) * 1024 + n]);
    g_bfrag[idx] = v;
}

// ---------------- main fused kernel ----------------
__global__ void __launch_bounds__(NTHREADS, 1)
fused_mlp_kernel(const float* __restrict__ emb,
                 const int*   __restrict__ idxg,
                 const int*   __restrict__ idxd,
                 const float* __restrict__ b1,
                 const float* __restrict__ W2,
                 const float* __restrict__ b2,
                 float*       __restrict__ out) {
    extern __shared__ char smem[];
    const int tid   = threadIdx.x;
    const int wid   = tid >> 5;
    const int lane  = tid & 31;
    const int mwarp = wid & 3;        // 0..3 -> rows mwarp*32
    const int nwarp = wid >> 2;       // 0..1 -> cols nwarp*16 within chunk
    const int base  = blockIdx.x * TILE_M;

    // ---- stage idx / b1 / W2 ----
    if (tid < 128)      ((int*)(smem + OFF_IDX))[tid] = idxg[base + tid];
    else                ((int*)(smem + OFF_IDX))[tid] = idxd[base + tid - 128];
    for (int i = tid; i < 1024; i += NTHREADS)
        ((float*)(smem + OFF_B1))[i] = b1[i];
    for (int i = tid; i < 1024; i += NTHREADS)
        ((float2*)(smem + OFF_W2))[i] = ((const float2*)W2)[i];
    __syncthreads();

    // ---- gather A into fragment-order smem ----
    // A frag layout: [ks(32)][mt(8)][lane(32)] float4{a0,a1,a2,a3}
    //   a0=(r,c) a1=(r+8,c) a2=(r,c+4) a3=(r+8,c+4); r=lane/4, c=lane%4 within tile
    {
        const int* idxs = (const int*)(smem + OFF_IDX);
        float* As = (float*)(smem + OFF_A);
        for (int i = tid; i < 8192; i += NTHREADS) {     // 8192 float4 loads
            int m = i >> 6;
            int q = i & 63;
            int half = q >> 5;
            int c4   = q & 31;
            int node = idxs[half * 128 + m];
            float4 v = *(const float4*)(emb + (size_t)node * 128 + (size_t)c4 * 4);
            v.x = ftf32(v.x); v.y = ftf32(v.y); v.z = ftf32(v.z); v.w = ftf32(v.w);
            int k0 = half * 128 + c4 * 4;
            int ks = k0 >> 3;
            int hi4 = (k0 >> 2) & 1;                     // cols 4..7 of the kstep?
            int mt = m >> 4;
            int mrow = m & 15;
            int laneBase = (mrow & 7) * 4;
            int slot = (mrow >= 8 ? 1 : 0) + (hi4 ? 2 : 0);
            float* dst = As + (((ks * 8 + mt) * 32 + laneBase) * 4 + slot);
            dst[0]  = v.x;
            dst[4]  = v.y;
            dst[8]  = v.z;
            dst[12] = v.w;
        }
    }

    // ---- preload B chunk 0 ----
    const char* bsrc_base = (const char*)g_bfrag;
    {
        uint32_t dst0 = smem_u32(smem + OFF_B);
#pragma unroll
        for (int j = 0; j < 8; j++) {
            int L = tid + j * NTHREADS;                  // 0..2047
            CP_ASYNC16(dst0 + L * 16, bsrc_base + L * 16);
        }
        CP_COMMIT();
    }

    const float*  b1s = (const float*)(smem + OFF_B1);
    const float2* w2s = (const float2*)(smem + OFF_W2);
    float2 o[4];
    o[0] = make_float2(0.f, 0.f); o[1] = make_float2(0.f, 0.f);
    o[2] = make_float2(0.f, 0.f); o[3] = make_float2(0.f, 0.f);

    int cur = 0;
    for (int nc = 0; nc < NCHUNKS; nc++) {
        // issue next chunk into the other buffer
        if (nc + 1 < NCHUNKS) {
            uint32_t dstn = smem_u32(smem + OFF_B + (cur ^ 1) * 32768);
            const char* srcn = bsrc_base + (size_t)(nc + 1) * 32768;
#pragma unroll
            for (int j = 0; j < 8; j++) {
                int L = tid + j * NTHREADS;
                CP_ASYNC16(dstn + L * 16, srcn + L * 16);
            }
            CP_COMMIT();
            CP_WAIT(1);
        } else {
            CP_WAIT(0);
        }
        __syncthreads();

        // ---- MMA over 32 ksteps ----
        float acc[2][2][4];
#pragma unroll
        for (int mti = 0; mti < 2; mti++)
#pragma unroll
            for (int ti = 0; ti < 2; ti++)
#pragma unroll
                for (int s = 0; s < 4; s++) acc[mti][ti][s] = 0.f;

        const uint4* Af = (const uint4*)(smem + OFF_A);
        const uint2* Bf = (const uint2*)(smem + OFF_B + cur * 32768);
#pragma unroll 8
        for (int ks = 0; ks < KSTEPS; ks++) {
            uint4 a0 = Af[(ks * 8 + mwarp * 2 + 0) * 32 + lane];
            uint4 a1 = Af[(ks * 8 + mwarp * 2 + 1) * 32 + lane];
            uint2 b0 = Bf[(ks * 4 + nwarp * 2 + 0) * 32 + lane];
            uint2 b1f = Bf[(ks * 4 + nwarp * 2 + 1) * 32 + lane];
            mma_tf32(acc[0][0][0], acc[0][0][1], acc[0][0][2], acc[0][0][3],
                     a0.x, a0.y, a0.z, a0.w, b0.x, b0.y);
            mma_tf32(acc[0][1][0], acc[0][1][1], acc[0][1][2], acc[0][1][3],
                     a0.x, a0.y, a0.z, a0.w, b1f.x, b1f.y);
            mma_tf32(acc[1][0][0], acc[1][0][1], acc[1][0][2], acc[1][0][3],
                     a1.x, a1.y, a1.z, a1.w, b0.x, b0.y);
            mma_tf32(acc[1][1][0], acc[1][1][1], acc[1][1][2], acc[1][1][3],
                     a1.x, a1.y, a1.z, a1.w, b1f.x, b1f.y);
        }
        __syncthreads();   // B buffer consumed; next iter may overwrite

        // ---- fused epilogue: +b1, GELU, x W2 accumulate ----
        int jbase = nc * 32 + nwarp * 16 + 2 * (lane & 3);
#pragma unroll
        for (int mti = 0; mti < 2; mti++) {
#pragma unroll
            for (int ti = 0; ti < 2; ti++) {
#pragma unroll
                for (int s = 0; s < 4; s++) {
                    int j = jbase + ti * 8 + (s & 1);
                    float h = acc[mti][ti][s] + b1s[j];
                    float g = gelu_exact(h);
                    float2 w = w2s[j];
                    int oi = mti * 2 + (s >> 1);
                    o[oi].x = fmaf(g, w.x, o[oi].x);
                    o[oi].y = fmaf(g, w.y, o[oi].y);
                }
            }
        }
        cur ^= 1;
    }

    // ---- reduce within quads (lanes sharing a row) ----
#pragma unroll
    for (int oi = 0; oi < 4; oi++) {
        o[oi].x += __shfl_xor_sync(0xFFFFFFFFu, o[oi].x, 1);
        o[oi].x += __shfl_xor_sync(0xFFFFFFFFu, o[oi].x, 2);
        o[oi].y += __shfl_xor_sync(0xFFFFFFFFu, o[oi].y, 1);
        o[oi].y += __shfl_xor_sync(0xFFFFFFFFu, o[oi].y, 2);
    }

    // ---- combine the two n-warps, add b2, write out ----
    float2* cmb = (float2*)(smem + OFF_CMB);
    int g = lane >> 2;
    __syncthreads();
    if (nwarp == 1 && (lane & 3) == 0) {
#pragma unroll
        for (int oi = 0; oi < 4; oi++) {
            int r = mwarp * 32 + (oi >> 1) * 16 + (oi & 1) * 8 + g;
            cmb[r] = o[oi];
        }
    }
    __syncthreads();
    if (nwarp == 0 && (lane & 3) == 0) {
        float b20 = __ldg(&b2[0]);
        float b21 = __ldg(&b2[1]);
#pragma unroll
        for (int oi = 0; oi < 4; oi++) {
            int r = mwarp * 32 + (oi >> 1) * 16 + (oi & 1) * 8 + g;
            float2 c = cmb[r];
            float2 res;
            res.x = o[oi].x + c.x + b20;
            res.y = o[oi].y + c.y + b21;
            ((float2*)out)[base + r] = res;
        }
    }
}

// ---------------- launch ----------------
extern "C" void kernel_launch(void* const* d_in, const int* in_sizes, int n_in,
                              void* d_out, int out_size) {
    const float* emb  = (const float*)d_in[0];
    const int*   idxg = (const int*)d_in[1];
    const int*   idxd = (const int*)d_in[2];
    const float* W1   = (const float*)d_in[3];
    const float* b1   = (const float*)d_in[4];
    const float* W2   = (const float*)d_in[5];
    const float* b2   = (const float*)d_in[6];
    float* out = (float*)d_out;

    static bool configured = false;
    if (!configured) {
        cudaFuncSetAttribute(fused_mlp_kernel,
                             cudaFuncAttributeMaxDynamicSharedMemorySize, SMEM_BYTES);
        configured = true;
    }

    prep_bfrag_kernel<<<512, 256>>>(W1);
    fused_mlp_kernel<<<2048, NTHREADS, SMEM_BYTES>>>(emb, idxg, idxd, b1, W2, b2, out);
}

// round 6
// speedup vs baseline: 1.1989x; 1.1989x over previous
// Fused gather+concat -> Linear(256,1024) -> exact GELU -> Linear(1024,2)
// sm_100 legacy mma.sync m16n8k8 tf32.
// R5 (resubmit; previous bench died to container infra, not the kernel):
// N-groups of 128 cols with 64 register accumulators/thread; B streamed
// through 2x32KB cp.async double buffer (linear 1MB stream of 32 blocks).
// A fragments smem-resident (loaded once). Warp tile 32x64 (4m x 2n).
// LDS traffic per CTA: ~7.3MB (was ~13.4MB in R4).

#include <cuda_runtime.h>
#include <cstdint>

#define NTHREADS   256
#define TILE_M     128
#define NGROUPS    8           // 1024 / 128
#define NKB        4           // K blocks per group-sweep: 4 x 64 = 256
#define NBLOCKS    32          // ngroups * nkb, linear B stream

// smem layout (bytes)
#define OFF_IDX    0           // 256 ints
#define OFF_CMB    1024        // 128 float2
#define OFF_B1     2048        // 1024 f32
#define OFF_W2     6144        // 1024 float2
#define OFF_A      14336       // A frags: 32 ksteps x 8 mtiles x 32 lanes x 16B = 131072
#define OFF_B      145408      // 2 x 32KB B block buffers
#define SMEM_BYTES 210944

// ---------------- helpers ----------------
__device__ __forceinline__ uint32_t smem_u32(const void* p) {
    uint32_t a;
    asm("{ .reg .u64 t; cvta.to.shared.u64 t, %1; cvt.u32.u64 %0, t; }"
        : "=r"(a) : "l"(p));
    return a;
}

#define CP_ASYNC16(dst, src) \
    asm volatile("cp.async.cg.shared.global [%0], [%1], 16;" :: "r"(dst), "l"(src))
#define CP_COMMIT() asm volatile("cp.async.commit_group;" ::: "memory")
#define CP_WAIT(n)  asm volatile("cp.async.wait_group %0;" :: "n"(n) : "memory")

// tf32 round-to-nearest; destination must be a b32 register
__device__ __forceinline__ float ftf32(float x) {
    uint32_t r;
    asm("cvt.rna.tf32.f32 %0, %1;" : "=r"(r) : "f"(x));
    return __uint_as_float(r);
}

__device__ __forceinline__ void mma_tf32(float* c,
                                         uint32_t a0, uint32_t a1, uint32_t a2, uint32_t a3,
                                         uint32_t b0, uint32_t b1) {
    asm volatile("mma.sync.aligned.m16n8k8.row.col.f32.tf32.tf32.f32 "
                 "{%0,%1,%2,%3}, {%4,%5,%6,%7}, {%8,%9}, {%0,%1,%2,%3};"
                 : "+f"(c[0]), "+f"(c[1]), "+f"(c[2]), "+f"(c[3])
                 : "r"(a0), "r"(a1), "r"(a2), "r"(a3), "r"(b0), "r"(b1));
}

// GELU with exact erf via A&S 7.1.26 (|eps| < 1.5e-7)
__device__ __forceinline__ float gelu_exact(float x) {
    float z = fabsf(x) * 0.70710678118654752f;
    float den = fmaf(z, 0.3275911f, 1.0f);
    float t; asm("rcp.approx.f32 %0, %1;" : "=f"(t) : "f"(den));
    float e = __expf(-z * z);
    float p = t * fmaf(t, fmaf(t, fmaf(t, fmaf(t, 0.5307027145f, -0.7265760135f),
                                       0.7107068705f), -0.142248368f), 0.127414796f);
    float q = p * e;                        // 0.5*(1-erf(z))
    float sc = copysignf(1.0f, x);
    float phi = fmaf(sc, 0.5f - q, 0.5f);   // Phi(x)
    return x * phi;
}

// ---------------- W1 -> fragment-pair-order gmem (prep) ----------------
// Layout: [blk(32)][ks(8)][np(8)][lane(32)] float4{b0_lo, b0_hi, b1_lo, b1_hi}
//   blk = ng*4 + kb ; K = kb*64 + ks*8 + lane%4 ; n = ng*128 + np*16 + lane/4
//   x = W1[K][n]   y = W1[K+4][n]   z = W1[K][n+8]   w = W1[K+4][n+8]
__device__ __align__(16) float4 g_bfrag[65536];

__global__ void prep_bfrag_kernel(const float* __restrict__ W1) {
    int idx = blockIdx.x * blockDim.x + threadIdx.x;   // 0 .. 65535
    int lane = idx & 31;
    int np   = (idx >> 5) & 7;
    int ks   = (idx >> 8) & 7;
    int blk  = idx >> 11;                              // 0..31
    int ng = blk >> 2;
    int kb = blk & 3;
    int k = kb * 64 + ks * 8 + (lane & 3);
    int n = ng * 128 + np * 16 + (lane >> 2);
    float4 v;
    v.x = ftf32(W1[k * 1024 + n]);
    v.y = ftf32(W1[(k + 4) * 1024 + n]);
    v.z = ftf32(W1[k * 1024 + n + 8]);
    v.w = ftf32(W1[(k + 4) * 1024 + n + 8]);
    g_bfrag[idx] = v;
}

// ---------------- main fused kernel ----------------
__global__ void __launch_bounds__(NTHREADS, 1)
fused_mlp_kernel(const float* __restrict__ emb,
                 const int*   __restrict__ idxg,
                 const int*   __restrict__ idxd,
                 const float* __restrict__ b1,
                 const float* __restrict__ W2,
                 const float* __restrict__ b2,
                 float*       __restrict__ out) {
    extern __shared__ char smem[];
    const int tid   = threadIdx.x;
    const int wid   = tid >> 5;
    const int lane  = tid & 31;
    const int mwarp = wid & 3;        // 0..3 -> rows mwarp*32
    const int nwarp = wid >> 2;       // 0..1 -> cols nwarp*64 within group
    const int base  = blockIdx.x * TILE_M;

    // ---- stage idx / b1 / W2 ----
    if (tid < 128)      ((int*)(smem + OFF_IDX))[tid] = idxg[base + tid];
    else                ((int*)(smem + OFF_IDX))[tid] = idxd[base + tid - 128];
    for (int i = tid; i < 1024; i += NTHREADS)
        ((float*)(smem + OFF_B1))[i] = b1[i];
    for (int i = tid; i < 1024; i += NTHREADS)
        ((float2*)(smem + OFF_W2))[i] = ((const float2*)W2)[i];
    __syncthreads();

    // ---- gather A into fragment-order smem (layout as R4, verified) ----
    // [ksg(32)][mt(8)][lane(32)] float4 {a0,a1,a2,a3}
    {
        const int* idxs = (const int*)(smem + OFF_IDX);
        float* As = (float*)(smem + OFF_A);
        for (int i = tid; i < 8192; i += NTHREADS) {
            int m = i >> 6;
            int q = i & 63;
            int half = q >> 5;
            int c4   = q & 31;
            int node = idxs[half * 128 + m];
            float4 v = *(const float4*)(emb + (size_t)node * 128 + (size_t)c4 * 4);
            v.x = ftf32(v.x); v.y = ftf32(v.y); v.z = ftf32(v.z); v.w = ftf32(v.w);
            int k0 = half * 128 + c4 * 4;
            int ksg = k0 >> 3;
            int hi4 = (k0 >> 2) & 1;
            int mt = m >> 4;
            int mrow = m & 15;
            int laneBase = (mrow & 7) * 4;
            int slot = (mrow >= 8 ? 1 : 0) + (hi4 ? 2 : 0);
            float* dst = As + (((ksg * 8 + mt) * 32 + laneBase) * 4 + slot);
            dst[0]  = v.x;
            dst[4]  = v.y;
            dst[8]  = v.z;
            dst[12] = v.w;
        }
    }

    // ---- preload B block 0 ----
    const char* bsrc = (const char*)g_bfrag;
    {
        uint32_t dst0 = smem_u32(smem + OFF_B);
#pragma unroll
        for (int j = 0; j < 8; j++) {
            int L = tid + j * NTHREADS;                  // 0..2047 x16B = 32KB
            CP_ASYNC16(dst0 + L * 16, bsrc + L * 16);
        }
        CP_COMMIT();
    }

    const float*  b1s = (const float*)(smem + OFF_B1);
    const float2* w2s = (const float2*)(smem + OFF_W2);
    float2 o[4];
    o[0] = make_float2(0.f, 0.f); o[1] = make_float2(0.f, 0.f);
    o[2] = make_float2(0.f, 0.f); o[3] = make_float2(0.f, 0.f);

    const uint4* Af = (const uint4*)(smem + OFF_A);

    for (int ng = 0; ng < NGROUPS; ng++) {
        float acc[2][8][4];
#pragma unroll
        for (int mt = 0; mt < 2; mt++)
#pragma unroll
            for (int nt = 0; nt < 8; nt++)
#pragma unroll
                for (int s = 0; s < 4; s++) acc[mt][nt][s] = 0.f;

        for (int kb = 0; kb < NKB; kb++) {
            int blk = ng * NKB + kb;
            // prefetch next block into the other buffer
            if (blk + 1 < NBLOCKS) {
                uint32_t dstn = smem_u32(smem + OFF_B + ((blk + 1) & 1) * 32768);
                const char* srcn = bsrc + (size_t)(blk + 1) * 32768;
#pragma unroll
                for (int j = 0; j < 8; j++) {
                    int L = tid + j * NTHREADS;
                    CP_ASYNC16(dstn + L * 16, srcn + L * 16);
                }
                CP_COMMIT();
                CP_WAIT(1);
            } else {
                CP_WAIT(0);
            }
            __syncthreads();   // block blk visible to all warps

            const float4* Bf = (const float4*)(smem + OFF_B + (blk & 1) * 32768);
#pragma unroll
            for (int ks = 0; ks < 8; ks++) {
                int ksg = kb * 8 + ks;
                uint4 a0 = Af[(ksg * 8 + mwarp * 2 + 0) * 32 + lane];
                uint4 a1 = Af[(ksg * 8 + mwarp * 2 + 1) * 32 + lane];
#pragma unroll
                for (int p = 0; p < 4; p++) {
                    float4 b = Bf[(ks * 8 + nwarp * 4 + p) * 32 + lane];
                    uint32_t blo0 = __float_as_uint(b.x), bhi0 = __float_as_uint(b.y);
                    uint32_t blo1 = __float_as_uint(b.z), bhi1 = __float_as_uint(b.w);
                    mma_tf32(acc[0][2 * p + 0], a0.x, a0.y, a0.z, a0.w, blo0, bhi0);
                    mma_tf32(acc[0][2 * p + 1], a0.x, a0.y, a0.z, a0.w, blo1, bhi1);
                    mma_tf32(acc[1][2 * p + 0], a1.x, a1.y, a1.z, a1.w, blo0, bhi0);
                    mma_tf32(acc[1][2 * p + 1], a1.x, a1.y, a1.z, a1.w, blo1, bhi1);
                }
            }
            __syncthreads();   // all warps done reading blk before blk+2 lands
        }

        // ---- fused epilogue: +b1, exact GELU, x W2 accumulate ----
        int jb = ng * 128 + nwarp * 64 + (lane & 3) * 2;
#pragma unroll
        for (int nt = 0; nt < 8; nt++) {
            int j = jb + nt * 8;
            float  bb0 = b1s[j],     bb1 = b1s[j + 1];
            float2 w0  = w2s[j];
            float2 w1  = w2s[j + 1];
#pragma unroll
            for (int mt = 0; mt < 2; mt++) {
#pragma unroll
                for (int sh = 0; sh < 2; sh++) {
                    int oi = mt * 2 + sh;
                    float g0 = gelu_exact(acc[mt][nt][sh * 2 + 0] + bb0);
                    float g1 = gelu_exact(acc[mt][nt][sh * 2 + 1] + bb1);
                    o[oi].x = fmaf(g0, w0.x, o[oi].x);
                    o[oi].y = fmaf(g0, w0.y, o[oi].y);
                    o[oi].x = fmaf(g1, w1.x, o[oi].x);
                    o[oi].y = fmaf(g1, w1.y, o[oi].y);
                }
            }
        }
    }

    // ---- reduce within quads (lanes sharing a row) ----
#pragma unroll
    for (int oi = 0; oi < 4; oi++) {
        o[oi].x += __shfl_xor_sync(0xFFFFFFFFu, o[oi].x, 1);
        o[oi].x += __shfl_xor_sync(0xFFFFFFFFu, o[oi].x, 2);
        o[oi].y += __shfl_xor_sync(0xFFFFFFFFu, o[oi].y, 1);
        o[oi].y += __shfl_xor_sync(0xFFFFFFFFu, o[oi].y, 2);
    }

    // ---- combine the two n-warps, add b2, write out ----
    float2* cmb = (float2*)(smem + OFF_CMB);
    int g = lane >> 2;
    __syncthreads();
    if (nwarp == 1 && (lane & 3) == 0) {
#pragma unroll
        for (int oi = 0; oi < 4; oi++) {
            int r = mwarp * 32 + (oi >> 1) * 16 + (oi & 1) * 8 + g;
            cmb[r] = o[oi];
        }
    }
    __syncthreads();
    if (nwarp == 0 && (lane & 3) == 0) {
        float b20 = __ldg(&b2[0]);
        float b21 = __ldg(&b2[1]);
#pragma unroll
        for (int oi = 0; oi < 4; oi++) {
            int r = mwarp * 32 + (oi >> 1) * 16 + (oi & 1) * 8 + g;
            float2 c = cmb[r];
            float2 res;
            res.x = o[oi].x + c.x + b20;
            res.y = o[oi].y + c.y + b21;
            ((float2*)out)[base + r] = res;
        }
    }
}

// ---------------- launch ----------------
extern "C" void kernel_launch(void* const* d_in, const int* in_sizes, int n_in,
                              void* d_out, int out_size) {
    const float* emb  = (const float*)d_in[0];
    const int*   idxg = (const int*)d_in[1];
    const int*   idxd = (const int*)d_in[2];
    const float* W1   = (const float*)d_in[3];
    const float* b1   = (const float*)d_in[4];
    const float* W2   = (const float*)d_in[5];
    const float* b2   = (const float*)d_in[6];
    float* out = (float*)d_out;

    static bool configured = false;
    if (!configured) {
        cudaFuncSetAttribute(fused_mlp_kernel,
                             cudaFuncAttributeMaxDynamicSharedMemorySize, SMEM_BYTES);
        configured = true;
    }

    prep_bfrag_kernel<<<256, 256>>>(W1);
    fused_mlp_kernel<<<2048, NTHREADS, SMEM_BYTES>>>(emb, idxg, idxd, b1, W2, b2, out);
}

// round 8
// speedup vs baseline: 1.7786x; 1.4836x over previous
// Fused gather+concat -> Linear(256,1024) -> exact GELU -> Linear(1024,2)
// sm_100 legacy mma.sync, R7 (resubmit; container infra failed, not kernel):
// fp16 m16n8k16 (same 10-bit mantissa as tf32, 2x K per instruction ->
// half the HMMAs and half the operand bytes).
// N-groups of 128 cols, 64 fp32 accumulators/thread; B streamed through
// 2x16KB cp.async double buffer (512KB linear stream of 32 blocks).
// A fragments smem-resident fp16 (64KB). Warp tile 32x64 (4m x 2n).

#include <cuda_runtime.h>
#include <cuda_fp16.h>
#include <cstdint>

#define NTHREADS   256
#define TILE_M     128
#define NGROUPS    8           // 1024 / 128
#define NKB        4           // K blocks per group-sweep: 4 x 64 = 256
#define NBLOCKS    32          // ngroups * nkb, linear B stream

// smem layout (bytes)
#define OFF_IDX    0           // 256 ints
#define OFF_CMB    1024        // 128 float2
#define OFF_B1     2048        // 1024 f32
#define OFF_W2     6144        // 1024 float2
#define OFF_A      14336       // A frags: 16 ksteps x 8 mtiles x 32 lanes x 16B = 65536
#define OFF_B      79872       // 2 x 16KB B block buffers
#define SMEM_BYTES 112640

// ---------------- helpers ----------------
__device__ __forceinline__ uint32_t smem_u32(const void* p) {
    uint32_t a;
    asm("{ .reg .u64 t; cvta.to.shared.u64 t, %1; cvt.u32.u64 %0, t; }"
        : "=r"(a) : "l"(p));
    return a;
}

#define CP_ASYNC16(dst, src) \
    asm volatile("cp.async.cg.shared.global [%0], [%1], 16;" :: "r"(dst), "l"(src))
#define CP_COMMIT() asm volatile("cp.async.commit_group;" ::: "memory")
#define CP_WAIT(n)  asm volatile("cp.async.wait_group %0;" :: "n"(n) : "memory")

// pack two f32 -> f16x2 (lo = first arg), round-to-nearest
__device__ __forceinline__ uint32_t packh2(float lo, float hi) {
    uint32_t w;
    asm("cvt.rn.f16x2.f32 %0, %1, %2;" : "=r"(w) : "f"(hi), "f"(lo));
    return w;
}

__device__ __forceinline__ void mma_f16(float* c,
                                        uint32_t a0, uint32_t a1, uint32_t a2, uint32_t a3,
                                        uint32_t b0, uint32_t b1) {
    asm volatile("mma.sync.aligned.m16n8k16.row.col.f32.f16.f16.f32 "
                 "{%0,%1,%2,%3}, {%4,%5,%6,%7}, {%8,%9}, {%0,%1,%2,%3};"
                 : "+f"(c[0]), "+f"(c[1]), "+f"(c[2]), "+f"(c[3])
                 : "r"(a0), "r"(a1), "r"(a2), "r"(a3), "r"(b0), "r"(b1));
}

// GELU with exact erf via A&S 7.1.26 (|eps| < 1.5e-7)
__device__ __forceinline__ float gelu_exact(float x) {
    float z = fabsf(x) * 0.70710678118654752f;
    float den = fmaf(z, 0.3275911f, 1.0f);
    float t; asm("rcp.approx.f32 %0, %1;" : "=f"(t) : "f"(den));
    float e = __expf(-z * z);
    float p = t * fmaf(t, fmaf(t, fmaf(t, fmaf(t, 0.5307027145f, -0.7265760135f),
                                       0.7107068705f), -0.142248368f), 0.127414796f);
    float q = p * e;                        // 0.5*(1-erf(z))
    float sc = copysignf(1.0f, x);
    float phi = fmaf(sc, 0.5f - q, 0.5f);   // Phi(x)
    return x * phi;
}

// ---------------- W1 -> fp16 fragment-pair-order gmem (prep) ----------------
// Layout: [blk(32)][ks(4)][np(8)][lane(32)] uint4{b0_lo, b0_hi, b1_lo, b1_hi}
//   blk = ng*4 + kb ; k = kb*64 + ks*16 + (lane%4)*2 ; n = ng*128 + np*16 + lane/4
//   b0_lo = h2(W1[k][n],   W1[k+1][n])   b0_hi = h2(W1[k+8][n],   W1[k+9][n])
//   b1_lo = h2(W1[k][n+8], W1[k+1][n+8]) b1_hi = h2(W1[k+8][n+8], W1[k+9][n+8])
__device__ __align__(16) uint4 g_bfrag[32768];

__global__ void prep_bfrag_kernel(const float* __restrict__ W1) {
    int idx = blockIdx.x * blockDim.x + threadIdx.x;   // 0 .. 32767
    int lane = idx & 31;
    int np   = (idx >> 5) & 7;
    int ks   = (idx >> 8) & 3;
    int blk  = idx >> 10;                              // 0..31
    int ng = blk >> 2;
    int kb = blk & 3;
    int k = kb * 64 + ks * 16 + (lane & 3) * 2;
    int n = ng * 128 + np * 16 + (lane >> 2);
    uint4 v;
    v.x = packh2(W1[k * 1024 + n],        W1[(k + 1) * 1024 + n]);
    v.y = packh2(W1[(k + 8) * 1024 + n],  W1[(k + 9) * 1024 + n]);
    v.z = packh2(W1[k * 1024 + n + 8],    W1[(k + 1) * 1024 + n + 8]);
    v.w = packh2(W1[(k + 8) * 1024 + n + 8], W1[(k + 9) * 1024 + n + 8]);
    g_bfrag[idx] = v;
}

// ---------------- main fused kernel ----------------
__global__ void __launch_bounds__(NTHREADS, 1)
fused_mlp_kernel(const float* __restrict__ emb,
                 const int*   __restrict__ idxg,
                 const int*   __restrict__ idxd,
                 const float* __restrict__ b1,
                 const float* __restrict__ W2,
                 const float* __restrict__ b2,
                 float*       __restrict__ out) {
    extern __shared__ char smem[];
    const int tid   = threadIdx.x;
    const int wid   = tid >> 5;
    const int lane  = tid & 31;
    const int mwarp = wid & 3;        // 0..3 -> rows mwarp*32
    const int nwarp = wid >> 2;       // 0..1 -> cols nwarp*64 within group
    const int base  = blockIdx.x * TILE_M;

    // ---- stage idx / b1 / W2 ----
    if (tid < 128)      ((int*)(smem + OFF_IDX))[tid] = idxg[base + tid];
    else                ((int*)(smem + OFF_IDX))[tid] = idxd[base + tid - 128];
    for (int i = tid; i < 1024; i += NTHREADS)
        ((float*)(smem + OFF_B1))[i] = b1[i];
    for (int i = tid; i < 1024; i += NTHREADS)
        ((float2*)(smem + OFF_W2))[i] = ((const float2*)W2)[i];
    __syncthreads();

    // ---- gather A into fp16 fragment-order smem ----
    // [ks(16)][mt(8)][lane(32)] uint4 {a0,a1,a2,a3} (m16n8k16 A layout)
    {
        const int* idxs = (const int*)(smem + OFF_IDX);
        uint32_t* As32 = (uint32_t*)(smem + OFF_A);
        for (int i = tid; i < 8192; i += NTHREADS) {
            int m = i >> 6;
            int q = i & 63;
            int half_ = q >> 5;
            int c4    = q & 31;
            int node = idxs[half_ * 128 + m];
            float4 v = *(const float4*)(emb + (size_t)node * 128 + (size_t)c4 * 4);
            uint32_t w0 = packh2(v.x, v.y);    // cols (k, k+1)
            uint32_t w1 = packh2(v.z, v.w);    // cols (k+2, k+3)
            int kg  = half_ * 128 + c4 * 4;    // global K, multiple of 4
            int ks  = kg >> 4;                 // 0..15
            int kin = kg & 15;                 // 0,4,8,12
            int q0  = kin >> 1;                // pair index 0,2,4,6
            int clow = q0 & 3;                 // tig for w0 (0 or 2); w1 -> +1
            int slot = (((m & 15) >= 8) ? 1 : 0) + ((q0 >= 4) ? 2 : 0);
            int mt = m >> 4;
            int lane0 = (m & 7) * 4 + clow;
            uint32_t* dst = As32 + (((ks * 8 + mt) * 32 + lane0) << 2) + slot;
            dst[0] = w0;
            dst[4] = w1;                       // next lane, same slot
        }
    }

    // ---- preload B block 0 ----
    const char* bsrc = (const char*)g_bfrag;
    {
        uint32_t dst0 = smem_u32(smem + OFF_B);
#pragma unroll
        for (int j = 0; j < 4; j++) {
            int L = tid + j * NTHREADS;                  // 0..1023 x16B = 16KB
            CP_ASYNC16(dst0 + L * 16, bsrc + L * 16);
        }
        CP_COMMIT();
    }

    const float*  b1s = (const float*)(smem + OFF_B1);
    const float2* w2s = (const float2*)(smem + OFF_W2);
    float2 o[4];
    o[0] = make_float2(0.f, 0.f); o[1] = make_float2(0.f, 0.f);
    o[2] = make_float2(0.f, 0.f); o[3] = make_float2(0.f, 0.f);

    const uint4* Af = (const uint4*)(smem + OFF_A);

    for (int ng = 0; ng < NGROUPS; ng++) {
        float acc[2][8][4];
#pragma unroll
        for (int mt = 0; mt < 2; mt++)
#pragma unroll
            for (int nt = 0; nt < 8; nt++)
#pragma unroll
                for (int s = 0; s < 4; s++) acc[mt][nt][s] = 0.f;

        for (int kb = 0; kb < NKB; kb++) {
            int blk = ng * NKB + kb;
            // prefetch next block into the other buffer
            if (blk + 1 < NBLOCKS) {
                uint32_t dstn = smem_u32(smem + OFF_B + ((blk + 1) & 1) * 16384);
                const char* srcn = bsrc + (size_t)(blk + 1) * 16384;
#pragma unroll
                for (int j = 0; j < 4; j++) {
                    int L = tid + j * NTHREADS;
                    CP_ASYNC16(dstn + L * 16, srcn + L * 16);
                }
                CP_COMMIT();
                CP_WAIT(1);
            } else {
                CP_WAIT(0);
            }
            __syncthreads();   // block blk visible to all warps

            const uint4* Bf = (const uint4*)(smem + OFF_B + (blk & 1) * 16384);
#pragma unroll
            for (int ks = 0; ks < 4; ks++) {
                int ksg = kb * 4 + ks;       // 0..15
                uint4 a0 = Af[(ksg * 8 + mwarp * 2 + 0) * 32 + lane];
                uint4 a1 = Af[(ksg * 8 + mwarp * 2 + 1) * 32 + lane];
#pragma unroll
                for (int p = 0; p < 4; p++) {
                    uint4 b = Bf[(ks * 8 + nwarp * 4 + p) * 32 + lane];
                    mma_f16(acc[0][2 * p + 0], a0.x, a0.y, a0.z, a0.w, b.x, b.y);
                    mma_f16(acc[0][2 * p + 1], a0.x, a0.y, a0.z, a0.w, b.z, b.w);
                    mma_f16(acc[1][2 * p + 0], a1.x, a1.y, a1.z, a1.w, b.x, b.y);
                    mma_f16(acc[1][2 * p + 1], a1.x, a1.y, a1.z, a1.w, b.z, b.w);
                }
            }
            __syncthreads();   // all warps done reading blk before blk+2 lands
        }

        // ---- fused epilogue: +b1, exact GELU, x W2 accumulate ----
        int jb = ng * 128 + nwarp * 64 + (lane & 3) * 2;
#pragma unroll
        for (int nt = 0; nt < 8; nt++) {
            int j = jb + nt * 8;
            float  bb0 = b1s[j],     bb1 = b1s[j + 1];
            float2 w0  = w2s[j];
            float2 w1  = w2s[j + 1];
#pragma unroll
            for (int mt = 0; mt < 2; mt++) {
#pragma unroll
                for (int sh = 0; sh < 2; sh++) {
                    int oi = mt * 2 + sh;
                    float g0 = gelu_exact(acc[mt][nt][sh * 2 + 0] + bb0);
                    float g1 = gelu_exact(acc[mt][nt][sh * 2 + 1] + bb1);
                    o[oi].x = fmaf(g0, w0.x, o[oi].x);
                    o[oi].y = fmaf(g0, w0.y, o[oi].y);
                    o[oi].x = fmaf(g1, w1.x, o[oi].x);
                    o[oi].y = fmaf(g1, w1.y, o[oi].y);
                }
            }
        }
    }

    // ---- reduce within quads (lanes sharing a row) ----
#pragma unroll
    for (int oi = 0; oi < 4; oi++) {
        o[oi].x += __shfl_xor_sync(0xFFFFFFFFu, o[oi].x, 1);
        o[oi].x += __shfl_xor_sync(0xFFFFFFFFu, o[oi].x, 2);
        o[oi].y += __shfl_xor_sync(0xFFFFFFFFu, o[oi].y, 1);
        o[oi].y += __shfl_xor_sync(0xFFFFFFFFu, o[oi].y, 2);
    }

    // ---- combine the two n-warps, add b2, write out ----
    float2* cmb = (float2*)(smem + OFF_CMB);
    int g = lane >> 2;
    __syncthreads();
    if (nwarp == 1 && (lane & 3) == 0) {
#pragma unroll
        for (int oi = 0; oi < 4; oi++) {
            int r = mwarp * 32 + (oi >> 1) * 16 + (oi & 1) * 8 + g;
            cmb[r] = o[oi];
        }
    }
    __syncthreads();
    if (nwarp == 0 && (lane & 3) == 0) {
        float b20 = __ldg(&b2[0]);
        float b21 = __ldg(&b2[1]);
#pragma unroll
        for (int oi = 0; oi < 4; oi++) {
            int r = mwarp * 32 + (oi >> 1) * 16 + (oi & 1) * 8 + g;
            float2 c = cmb[r];
            float2 res;
            res.x = o[oi].x + c.x + b20;
            res.y = o[oi].y + c.y + b21;
            ((float2*)out)[base + r] = res;
        }
    }
}

// ---------------- launch ----------------
extern "C" void kernel_launch(void* const* d_in, const int* in_sizes, int n_in,
                              void* d_out, int out_size) {
    const float* emb  = (const float*)d_in[0];
    const int*   idxg = (const int*)d_in[1];
    const int*   idxd = (const int*)d_in[2];
    const float* W1   = (const float*)d_in[3];
    const float* b1   = (const float*)d_in[4];
    const float* W2   = (const float*)d_in[5];
    const float* b2   = (const float*)d_in[6];
    float* out = (float*)d_out;

    static bool configured = false;
    if (!configured) {
        cudaFuncSetAttribute(fused_mlp_kernel,
                             cudaFuncAttributeMaxDynamicSharedMemorySize, SMEM_BYTES);
        configured = true;
    }

    prep_bfrag_kernel<<<128, 256>>>(W1);
    fused_mlp_kernel<<<2048, NTHREADS, SMEM_BYTES>>>(emb, idxg, idxd, b1, W2, b2, out);
}

// round 9
// speedup vs baseline: 2.0958x; 1.1783x over previous
// Fused gather+concat -> Linear(256,1024) -> exact GELU -> Linear(1024,2)
// sm_100 legacy mma.sync fp16 m16n8k16.
// R9: 2 CTAs/SM (__launch_bounds__(256,2)). N-groups shrink 128->64 cols so
// accumulators drop 64->32 regs (target <=128 regs) and smem drops to 94KB/CTA
// (188KB/SM). B streamed through 2x8KB cp.async double buffer (64-block
// linear stream). A fragments smem-resident fp16 (64KB). Warp tile 32x32.

#include <cuda_runtime.h>
#include <cuda_fp16.h>
#include <cstdint>

#define NTHREADS   256
#define TILE_M     128
#define NGROUPS    16          // 1024 / 64
#define NKB        4           // K blocks per group-sweep: 4 x 64 = 256
#define NBLOCKS    64          // ngroups * nkb, linear B stream
#define BBLK_BYTES 8192        // 64 K x 64 cols x 2B

// smem layout (bytes)
#define OFF_IDX    0           // 256 ints
#define OFF_CMB    1024        // 128 float2
#define OFF_B1     2048        // 1024 f32
#define OFF_W2     6144        // 1024 float2
#define OFF_A      14336       // A frags: 16 ksteps x 8 mtiles x 32 lanes x 16B = 65536
#define OFF_B      79872       // 2 x 8KB B block buffers
#define SMEM_BYTES 96256

// ---------------- helpers ----------------
__device__ __forceinline__ uint32_t smem_u32(const void* p) {
    uint32_t a;
    asm("{ .reg .u64 t; cvta.to.shared.u64 t, %1; cvt.u32.u64 %0, t; }"
        : "=r"(a) : "l"(p));
    return a;
}

#define CP_ASYNC16(dst, src) \
    asm volatile("cp.async.cg.shared.global [%0], [%1], 16;" :: "r"(dst), "l"(src))
#define CP_COMMIT() asm volatile("cp.async.commit_group;" ::: "memory")
#define CP_WAIT(n)  asm volatile("cp.async.wait_group %0;" :: "n"(n) : "memory")

// pack two f32 -> f16x2 (lo = first arg), round-to-nearest
__device__ __forceinline__ uint32_t packh2(float lo, float hi) {
    uint32_t w;
    asm("cvt.rn.f16x2.f32 %0, %1, %2;" : "=r"(w) : "f"(hi), "f"(lo));
    return w;
}

__device__ __forceinline__ void mma_f16(float* c,
                                        uint32_t a0, uint32_t a1, uint32_t a2, uint32_t a3,
                                        uint32_t b0, uint32_t b1) {
    asm volatile("mma.sync.aligned.m16n8k16.row.col.f32.f16.f16.f32 "
                 "{%0,%1,%2,%3}, {%4,%5,%6,%7}, {%8,%9}, {%0,%1,%2,%3};"
                 : "+f"(c[0]), "+f"(c[1]), "+f"(c[2]), "+f"(c[3])
                 : "r"(a0), "r"(a1), "r"(a2), "r"(a3), "r"(b0), "r"(b1));
}

// GELU with exact erf via A&S 7.1.26 (|eps| < 1.5e-7)
__device__ __forceinline__ float gelu_exact(float x) {
    float z = fabsf(x) * 0.70710678118654752f;
    float den = fmaf(z, 0.3275911f, 1.0f);
    float t; asm("rcp.approx.f32 %0, %1;" : "=f"(t) : "f"(den));
    float e = __expf(-z * z);
    float p = t * fmaf(t, fmaf(t, fmaf(t, fmaf(t, 0.5307027145f, -0.7265760135f),
                                       0.7107068705f), -0.142248368f), 0.127414796f);
    float q = p * e;                        // 0.5*(1-erf(z))
    float sc = copysignf(1.0f, x);
    float phi = fmaf(sc, 0.5f - q, 0.5f);   // Phi(x)
    return x * phi;
}

// ---------------- W1 -> fp16 fragment-pair-order gmem (prep) ----------------
// Layout: [blk(64)][ks(4)][np(4)][lane(32)] uint4{b0_lo, b0_hi, b1_lo, b1_hi}
//   blk = ng*4 + kb ; k = kb*64 + ks*16 + (lane%4)*2 ; n = ng*64 + np*16 + lane/4
//   b0_lo = h2(W1[k][n],   W1[k+1][n])   b0_hi = h2(W1[k+8][n],   W1[k+9][n])
//   b1_lo = h2(W1[k][n+8], W1[k+1][n+8]) b1_hi = h2(W1[k+8][n+8], W1[k+9][n+8])
__device__ __align__(16) uint4 g_bfrag[32768];

__global__ void prep_bfrag_kernel(const float* __restrict__ W1) {
    int idx = blockIdx.x * blockDim.x + threadIdx.x;   // 0 .. 32767
    int lane = idx & 31;
    int np   = (idx >> 5) & 3;
    int ks   = (idx >> 7) & 3;
    int blk  = idx >> 9;                               // 0..63
    int ng = blk >> 2;
    int kb = blk & 3;
    int k = kb * 64 + ks * 16 + (lane & 3) * 2;
    int n = ng * 64 + np * 16 + (lane >> 2);
    uint4 v;
    v.x = packh2(W1[k * 1024 + n],           W1[(k + 1) * 1024 + n]);
    v.y = packh2(W1[(k + 8) * 1024 + n],     W1[(k + 9) * 1024 + n]);
    v.z = packh2(W1[k * 1024 + n + 8],       W1[(k + 1) * 1024 + n + 8]);
    v.w = packh2(W1[(k + 8) * 1024 + n + 8], W1[(k + 9) * 1024 + n + 8]);
    g_bfrag[idx] = v;
}

// ---------------- main fused kernel ----------------
__global__ void __launch_bounds__(NTHREADS, 2)
fused_mlp_kernel(const float* __restrict__ emb,
                 const int*   __restrict__ idxg,
                 const int*   __restrict__ idxd,
                 const float* __restrict__ b1,
                 const float* __restrict__ W2,
                 const float* __restrict__ b2,
                 float*       __restrict__ out) {
    extern __shared__ char smem[];
    const int tid   = threadIdx.x;
    const int wid   = tid >> 5;
    const int lane  = tid & 31;
    const int mwarp = wid & 3;        // 0..3 -> rows mwarp*32
    const int nwarp = wid >> 2;       // 0..1 -> cols nwarp*32 within group
    const int base  = blockIdx.x * TILE_M;

    // ---- stage idx / b1 / W2 ----
    if (tid < 128)      ((int*)(smem + OFF_IDX))[tid] = idxg[base + tid];
    else                ((int*)(smem + OFF_IDX))[tid] = idxd[base + tid - 128];
    for (int i = tid; i < 1024; i += NTHREADS)
        ((float*)(smem + OFF_B1))[i] = b1[i];
    for (int i = tid; i < 1024; i += NTHREADS)
        ((float2*)(smem + OFF_W2))[i] = ((const float2*)W2)[i];
    __syncthreads();

    // ---- gather A into fp16 fragment-order smem ----
    // [ks(16)][mt(8)][lane(32)] uint4 {a0,a1,a2,a3} (m16n8k16 A layout)
    {
        const int* idxs = (const int*)(smem + OFF_IDX);
        uint32_t* As32 = (uint32_t*)(smem + OFF_A);
        for (int i = tid; i < 8192; i += NTHREADS) {
            int m = i >> 6;
            int q = i & 63;
            int half_ = q >> 5;
            int c4    = q & 31;
            int node = idxs[half_ * 128 + m];
            float4 v = *(const float4*)(emb + (size_t)node * 128 + (size_t)c4 * 4);
            uint32_t w0 = packh2(v.x, v.y);    // cols (k, k+1)
            uint32_t w1 = packh2(v.z, v.w);    // cols (k+2, k+3)
            int kg  = half_ * 128 + c4 * 4;    // global K, multiple of 4
            int ks  = kg >> 4;                 // 0..15
            int kin = kg & 15;                 // 0,4,8,12
            int q0  = kin >> 1;                // pair index 0,2,4,6
            int clow = q0 & 3;                 // lane low bits for w0; w1 -> +1
            int slot = (((m & 15) >= 8) ? 1 : 0) + ((q0 >= 4) ? 2 : 0);
            int mt = m >> 4;
            int lane0 = (m & 7) * 4 + clow;
            uint32_t* dst = As32 + (((ks * 8 + mt) * 32 + lane0) << 2) + slot;
            dst[0] = w0;
            dst[4] = w1;                       // next lane, same slot
        }
    }

    // ---- preload B block 0 ----
    const char* bsrc = (const char*)g_bfrag;
    {
        uint32_t dst0 = smem_u32(smem + OFF_B);
#pragma unroll
        for (int j = 0; j < 2; j++) {
            int L = tid + j * NTHREADS;                  // 0..511 x16B = 8KB
            CP_ASYNC16(dst0 + L * 16, bsrc + L * 16);
        }
        CP_COMMIT();
    }

    const float*  b1s = (const float*)(smem + OFF_B1);
    const float2* w2s = (const float2*)(smem + OFF_W2);
    float2 o[4];
    o[0] = make_float2(0.f, 0.f); o[1] = make_float2(0.f, 0.f);
    o[2] = make_float2(0.f, 0.f); o[3] = make_float2(0.f, 0.f);

    const uint4* Af = (const uint4*)(smem + OFF_A);

    for (int ng = 0; ng < NGROUPS; ng++) {
        float acc[2][4][4];
#pragma unroll
        for (int mt = 0; mt < 2; mt++)
#pragma unroll
            for (int nt = 0; nt < 4; nt++)
#pragma unroll
                for (int s = 0; s < 4; s++) acc[mt][nt][s] = 0.f;

        for (int kb = 0; kb < NKB; kb++) {
            int blk = ng * NKB + kb;
            // prefetch next block into the other buffer
            if (blk + 1 < NBLOCKS) {
                uint32_t dstn = smem_u32(smem + OFF_B + ((blk + 1) & 1) * BBLK_BYTES);
                const char* srcn = bsrc + (size_t)(blk + 1) * BBLK_BYTES;
#pragma unroll
                for (int j = 0; j < 2; j++) {
                    int L = tid + j * NTHREADS;
                    CP_ASYNC16(dstn + L * 16, srcn + L * 16);
                }
                CP_COMMIT();
                CP_WAIT(1);
            } else {
                CP_WAIT(0);
            }
            __syncthreads();   // block blk visible to all warps

            const uint4* Bf = (const uint4*)(smem + OFF_B + (blk & 1) * BBLK_BYTES);
#pragma unroll
            for (int ks = 0; ks < 4; ks++) {
                int ksg = kb * 4 + ks;       // 0..15
                uint4 a0 = Af[(ksg * 8 + mwarp * 2 + 0) * 32 + lane];
                uint4 a1 = Af[(ksg * 8 + mwarp * 2 + 1) * 32 + lane];
#pragma unroll
                for (int p = 0; p < 2; p++) {
                    uint4 b = Bf[(ks * 4 + nwarp * 2 + p) * 32 + lane];
                    mma_f16(acc[0][2 * p + 0], a0.x, a0.y, a0.z, a0.w, b.x, b.y);
                    mma_f16(acc[0][2 * p + 1], a0.x, a0.y, a0.z, a0.w, b.z, b.w);
                    mma_f16(acc[1][2 * p + 0], a1.x, a1.y, a1.z, a1.w, b.x, b.y);
                    mma_f16(acc[1][2 * p + 1], a1.x, a1.y, a1.z, a1.w, b.z, b.w);
                }
            }
            __syncthreads();   // all warps done reading blk before blk+2 lands
        }

        // ---- fused epilogue: +b1, exact GELU, x W2 accumulate ----
        int jb = ng * 64 + nwarp * 32 + (lane & 3) * 2;
#pragma unroll
        for (int nt = 0; nt < 4; nt++) {
            int j = jb + nt * 8;
            float  bb0 = b1s[j],     bb1 = b1s[j + 1];
            float2 w0  = w2s[j];
            float2 w1  = w2s[j + 1];
#pragma unroll
            for (int mt = 0; mt < 2; mt++) {
#pragma unroll
                for (int sh = 0; sh < 2; sh++) {
                    int oi = mt * 2 + sh;
                    float g0 = gelu_exact(acc[mt][nt][sh * 2 + 0] + bb0);
                    float g1 = gelu_exact(acc[mt][nt][sh * 2 + 1] + bb1);
                    o[oi].x = fmaf(g0, w0.x, o[oi].x);
                    o[oi].y = fmaf(g0, w0.y, o[oi].y);
                    o[oi].x = fmaf(g1, w1.x, o[oi].x);
                    o[oi].y = fmaf(g1, w1.y, o[oi].y);
                }
            }
        }
    }

    // ---- reduce within quads (lanes sharing a row) ----
#pragma unroll
    for (int oi = 0; oi < 4; oi++) {
        o[oi].x += __shfl_xor_sync(0xFFFFFFFFu, o[oi].x, 1);
        o[oi].x += __shfl_xor_sync(0xFFFFFFFFu, o[oi].x, 2);
        o[oi].y += __shfl_xor_sync(0xFFFFFFFFu, o[oi].y, 1);
        o[oi].y += __shfl_xor_sync(0xFFFFFFFFu, o[oi].y, 2);
    }

    // ---- combine the two n-warps, add b2, write out ----
    float2* cmb = (float2*)(smem + OFF_CMB);
    int g = lane >> 2;
    __syncthreads();
    if (nwarp == 1 && (lane & 3) == 0) {
#pragma unroll
        for (int oi = 0; oi < 4; oi++) {
            int r = mwarp * 32 + (oi >> 1) * 16 + (oi & 1) * 8 + g;
            cmb[r] = o[oi];
        }
    }
    __syncthreads();
    if (nwarp == 0 && (lane & 3) == 0) {
        float b20 = __ldg(&b2[0]);
        float b21 = __ldg(&b2[1]);
#pragma unroll
        for (int oi = 0; oi < 4; oi++) {
            int r = mwarp * 32 + (oi >> 1) * 16 + (oi & 1) * 8 + g;
            float2 c = cmb[r];
            float2 res;
            res.x = o[oi].x + c.x + b20;
            res.y = o[oi].y + c.y + b21;
            ((float2*)out)[base + r] = res;
        }
    }
}

// ---------------- launch ----------------
extern "C" void kernel_launch(void* const* d_in, const int* in_sizes, int n_in,
                              void* d_out, int out_size) {
    const float* emb  = (const float*)d_in[0];
    const int*   idxg = (const int*)d_in[1];
    const int*   idxd = (const int*)d_in[2];
    const float* W1   = (const float*)d_in[3];
    const float* b1   = (const float*)d_in[4];
    const float* W2   = (const float*)d_in[5];
    const float* b2   = (const float*)d_in[6];
    float* out = (float*)d_out;

    static bool configured = false;
    if (!configured) {
        cudaFuncSetAttribute(fused_mlp_kernel,
                             cudaFuncAttributeMaxDynamicSharedMemorySize, SMEM_BYTES);
        configured = true;
    }

    prep_bfrag_kernel<<<128, 256>>>(W1);
    fused_mlp_kernel<<<2048, NTHREADS, SMEM_BYTES>>>(emb, idxg, idxd, b1, W2, b2, out);
}

// round 11
// speedup vs baseline: 2.6425x; 1.2608x over previous
// Fused gather+concat -> Linear(256,1024) -> GELU -> Linear(1024,2)
// sm_100 legacy mma.sync fp16 m16n8k16, 2 CTAs/SM.
// R10 resubmit (container infra failed twice on identical source; R5/R7
// precedent: clean pass on resubmission).
// (a) GELU via tanh.approx.f32 MUFU (6 instrs vs ~14 for exact-erf poly)
// (b) 3-slot cp.async B ring with ONE __syncthreads per k-block (was 2).
// N-groups of 64 cols, 32 fp32 accumulators/thread, warp tile 32x32.

#include <cuda_runtime.h>
#include <cuda_fp16.h>
#include <cstdint>

#define NTHREADS   256
#define TILE_M     128
#define NGROUPS    16          // 1024 / 64
#define NKB        4           // K blocks per group-sweep: 4 x 64 = 256
#define NBLOCKS    64          // ngroups * nkb, linear B stream
#define BBLK_BYTES 8192        // 64 K x 64 cols x 2B

// smem layout (bytes)
#define OFF_IDX    0           // 256 ints
#define OFF_CMB    1024        // 128 float2
#define OFF_B1     2048        // 1024 f32
#define OFF_W2     6144        // 1024 float2
#define OFF_A      14336       // A frags: 16 ksteps x 8 mtiles x 32 lanes x 16B = 65536
#define OFF_B      79872       // 3 x 8KB B ring slots
#define SMEM_BYTES 104448

// ---------------- helpers ----------------
__device__ __forceinline__ uint32_t smem_u32(const void* p) {
    uint32_t a;
    asm("{ .reg .u64 t; cvta.to.shared.u64 t, %1; cvt.u32.u64 %0, t; }"
        : "=r"(a) : "l"(p));
    return a;
}

#define CP_ASYNC16(dst, src) \
    asm volatile("cp.async.cg.shared.global [%0], [%1], 16;" :: "r"(dst), "l"(src))
#define CP_COMMIT() asm volatile("cp.async.commit_group;" ::: "memory")
#define CP_WAIT(n)  asm volatile("cp.async.wait_group %0;" :: "n"(n) : "memory")

// pack two f32 -> f16x2 (lo = first arg), round-to-nearest
__device__ __forceinline__ uint32_t packh2(float lo, float hi) {
    uint32_t w;
    asm("cvt.rn.f16x2.f32 %0, %1, %2;" : "=r"(w) : "f"(hi), "f"(lo));
    return w;
}

__device__ __forceinline__ void mma_f16(float* c,
                                        uint32_t a0, uint32_t a1, uint32_t a2, uint32_t a3,
                                        uint32_t b0, uint32_t b1) {
    asm volatile("mma.sync.aligned.m16n8k16.row.col.f32.f16.f16.f32 "
                 "{%0,%1,%2,%3}, {%4,%5,%6,%7}, {%8,%9}, {%0,%1,%2,%3};"
                 : "+f"(c[0]), "+f"(c[1]), "+f"(c[2]), "+f"(c[3])
                 : "r"(a0), "r"(a1), "r"(a2), "r"(a3), "r"(b0), "r"(b1));
}

// GELU via tanh approximation + MUFU tanh (6 instrs):
// gelu(x) ~= x * (0.5 + 0.5*tanh(0.79788456*(x + 0.044715*x^3)))
__device__ __forceinline__ float gelu_fast(float x) {
    float t = x * x;
    float c = fmaf(t, 0.035677408136f, 0.7978845608028654f);
    float arg = x * c;
    float th;
    asm("tanh.approx.f32 %0, %1;" : "=f"(th) : "f"(arg));
    return x * fmaf(th, 0.5f, 0.5f);
}

// ---------------- W1 -> fp16 fragment-pair-order gmem (prep) ----------------
// Layout: [blk(64)][ks(4)][np(4)][lane(32)] uint4{b0_lo, b0_hi, b1_lo, b1_hi}
//   blk = ng*4 + kb ; k = kb*64 + ks*16 + (lane%4)*2 ; n = ng*64 + np*16 + lane/4
__device__ __align__(16) uint4 g_bfrag[32768];

__global__ void prep_bfrag_kernel(const float* __restrict__ W1) {
    int idx = blockIdx.x * blockDim.x + threadIdx.x;   // 0 .. 32767
    int lane = idx & 31;
    int np   = (idx >> 5) & 3;
    int ks   = (idx >> 7) & 3;
    int blk  = idx >> 9;                               // 0..63
    int ng = blk >> 2;
    int kb = blk & 3;
    int k = kb * 64 + ks * 16 + (lane & 3) * 2;
    int n = ng * 64 + np * 16 + (lane >> 2);
    uint4 v;
    v.x = packh2(W1[k * 1024 + n],           W1[(k + 1) * 1024 + n]);
    v.y = packh2(W1[(k + 8) * 1024 + n],     W1[(k + 9) * 1024 + n]);
    v.z = packh2(W1[k * 1024 + n + 8],       W1[(k + 1) * 1024 + n + 8]);
    v.w = packh2(W1[(k + 8) * 1024 + n + 8], W1[(k + 9) * 1024 + n + 8]);
    g_bfrag[idx] = v;
}

// ---------------- main fused kernel ----------------
__global__ void __launch_bounds__(NTHREADS, 2)
fused_mlp_kernel(const float* __restrict__ emb,
                 const int*   __restrict__ idxg,
                 const int*   __restrict__ idxd,
                 const float* __restrict__ b1,
                 const float* __restrict__ W2,
                 const float* __restrict__ b2,
                 float*       __restrict__ out) {
    extern __shared__ char smem[];
    const int tid   = threadIdx.x;
    const int wid   = tid >> 5;
    const int lane  = tid & 31;
    const int mwarp = wid & 3;        // 0..3 -> rows mwarp*32
    const int nwarp = wid >> 2;       // 0..1 -> cols nwarp*32 within group
    const int base  = blockIdx.x * TILE_M;

    // ---- stage idx / b1 / W2 ----
    if (tid < 128)      ((int*)(smem + OFF_IDX))[tid] = idxg[base + tid];
    else                ((int*)(smem + OFF_IDX))[tid] = idxd[base + tid - 128];
    for (int i = tid; i < 1024; i += NTHREADS)
        ((float*)(smem + OFF_B1))[i] = b1[i];
    for (int i = tid; i < 1024; i += NTHREADS)
        ((float2*)(smem + OFF_W2))[i] = ((const float2*)W2)[i];
    __syncthreads();

    // ---- gather A into fp16 fragment-order smem ----
    // [ks(16)][mt(8)][lane(32)] uint4 {a0,a1,a2,a3} (m16n8k16 A layout)
    {
        const int* idxs = (const int*)(smem + OFF_IDX);
        uint32_t* As32 = (uint32_t*)(smem + OFF_A);
        for (int i = tid; i < 8192; i += NTHREADS) {
            int m = i >> 6;
            int q = i & 63;
            int half_ = q >> 5;
            int c4    = q & 31;
            int node = idxs[half_ * 128 + m];
            float4 v = *(const float4*)(emb + (size_t)node * 128 + (size_t)c4 * 4);
            uint32_t w0 = packh2(v.x, v.y);    // cols (k, k+1)
            uint32_t w1 = packh2(v.z, v.w);    // cols (k+2, k+3)
            int kg  = half_ * 128 + c4 * 4;    // global K, multiple of 4
            int ks  = kg >> 4;                 // 0..15
            int kin = kg & 15;                 // 0,4,8,12
            int q0  = kin >> 1;                // pair index 0,2,4,6
            int clow = q0 & 3;                 // lane low bits for w0; w1 -> +1
            int slot = (((m & 15) >= 8) ? 1 : 0) + ((q0 >= 4) ? 2 : 0);
            int mt = m >> 4;
            int lane0 = (m & 7) * 4 + clow;
            uint32_t* dst = As32 + (((ks * 8 + mt) * 32 + lane0) << 2) + slot;
            dst[0] = w0;
            dst[4] = w1;                       // next lane, same slot
        }
    }

    // ---- preload B blocks 0 and 1 (two separate cp.async groups) ----
    const char* bsrc = (const char*)g_bfrag;
#pragma unroll
    for (int s = 0; s < 2; s++) {
        uint32_t dsts = smem_u32(smem + OFF_B + s * BBLK_BYTES);
        const char* srcs = bsrc + (size_t)s * BBLK_BYTES;
#pragma unroll
        for (int j = 0; j < 2; j++) {
            int L = tid + j * NTHREADS;                  // 0..511 x16B = 8KB
            CP_ASYNC16(dsts + L * 16, srcs + L * 16);
        }
        CP_COMMIT();
    }

    const float*  b1s = (const float*)(smem + OFF_B1);
    const float2* w2s = (const float2*)(smem + OFF_W2);
    float2 o[4];
    o[0] = make_float2(0.f, 0.f); o[1] = make_float2(0.f, 0.f);
    o[2] = make_float2(0.f, 0.f); o[3] = make_float2(0.f, 0.f);

    const uint4* Af = (const uint4*)(smem + OFF_A);
    int s_cur = 0;   // slot of current block (blk % 3)
    int s_pf  = 2;   // slot of block blk+2

    for (int ng = 0; ng < NGROUPS; ng++) {
        float acc[2][4][4];
#pragma unroll
        for (int mt = 0; mt < 2; mt++)
#pragma unroll
            for (int nt = 0; nt < 4; nt++)
#pragma unroll
                for (int s = 0; s < 4; s++) acc[mt][nt][s] = 0.f;

        for (int kb = 0; kb < NKB; kb++) {
            int blk = ng * NKB + kb;
            // wait until block blk resident (in flight: blk, blk+1)
            if (blk + 1 < NBLOCKS) { CP_WAIT(1); } else { CP_WAIT(0); }
            __syncthreads();   // also fences reads of slot written by next prefetch
            // prefetch block blk+2 into slot (blk+2)%3 (read at iter blk-1, safe)
            if (blk + 2 < NBLOCKS) {
                uint32_t dstn = smem_u32(smem + OFF_B + s_pf * BBLK_BYTES);
                const char* srcn = bsrc + (size_t)(blk + 2) * BBLK_BYTES;
#pragma unroll
                for (int j = 0; j < 2; j++) {
                    int L = tid + j * NTHREADS;
                    CP_ASYNC16(dstn + L * 16, srcn + L * 16);
                }
                CP_COMMIT();
            }

            const uint4* Bf = (const uint4*)(smem + OFF_B + s_cur * BBLK_BYTES);
#pragma unroll
            for (int ks = 0; ks < 4; ks++) {
                int ksg = kb * 4 + ks;       // 0..15
                uint4 a0 = Af[(ksg * 8 + mwarp * 2 + 0) * 32 + lane];
                uint4 a1 = Af[(ksg * 8 + mwarp * 2 + 1) * 32 + lane];
#pragma unroll
                for (int p = 0; p < 2; p++) {
                    uint4 b = Bf[(ks * 4 + nwarp * 2 + p) * 32 + lane];
                    mma_f16(acc[0][2 * p + 0], a0.x, a0.y, a0.z, a0.w, b.x, b.y);
                    mma_f16(acc[0][2 * p + 1], a0.x, a0.y, a0.z, a0.w, b.z, b.w);
                    mma_f16(acc[1][2 * p + 0], a1.x, a1.y, a1.z, a1.w, b.x, b.y);
                    mma_f16(acc[1][2 * p + 1], a1.x, a1.y, a1.z, a1.w, b.z, b.w);
                }
            }
            // advance ring
            s_cur = (s_cur == 2) ? 0 : s_cur + 1;
            s_pf  = (s_pf  == 2) ? 0 : s_pf  + 1;
        }

        // ---- fused epilogue: +b1, fast GELU, x W2 accumulate ----
        int jb = ng * 64 + nwarp * 32 + (lane & 3) * 2;
#pragma unroll
        for (int nt = 0; nt < 4; nt++) {
            int j = jb + nt * 8;
            float  bb0 = b1s[j],     bb1 = b1s[j + 1];
            float2 w0  = w2s[j];
            float2 w1  = w2s[j + 1];
#pragma unroll
            for (int mt = 0; mt < 2; mt++) {
#pragma unroll
                for (int sh = 0; sh < 2; sh++) {
                    int oi = mt * 2 + sh;
                    float g0 = gelu_fast(acc[mt][nt][sh * 2 + 0] + bb0);
                    float g1 = gelu_fast(acc[mt][nt][sh * 2 + 1] + bb1);
                    o[oi].x = fmaf(g0, w0.x, o[oi].x);
                    o[oi].y = fmaf(g0, w0.y, o[oi].y);
                    o[oi].x = fmaf(g1, w1.x, o[oi].x);
                    o[oi].y = fmaf(g1, w1.y, o[oi].y);
                }
            }
        }
    }

    // ---- reduce within quads (lanes sharing a row) ----
#pragma unroll
    for (int oi = 0; oi < 4; oi++) {
        o[oi].x += __shfl_xor_sync(0xFFFFFFFFu, o[oi].x, 1);
        o[oi].x += __shfl_xor_sync(0xFFFFFFFFu, o[oi].x, 2);
        o[oi].y += __shfl_xor_sync(0xFFFFFFFFu, o[oi].y, 1);
        o[oi].y += __shfl_xor_sync(0xFFFFFFFFu, o[oi].y, 2);
    }

    // ---- combine the two n-warps, add b2, write out ----
    float2* cmb = (float2*)(smem + OFF_CMB);
    int g = lane >> 2;
    __syncthreads();
    if (nwarp == 1 && (lane & 3) == 0) {
#pragma unroll
        for (int oi = 0; oi < 4; oi++) {
            int r = mwarp * 32 + (oi >> 1) * 16 + (oi & 1) * 8 + g;
            cmb[r] = o[oi];
        }
    }
    __syncthreads();
    if (nwarp == 0 && (lane & 3) == 0) {
        float b20 = __ldg(&b2[0]);
        float b21 = __ldg(&b2[1]);
#pragma unroll
        for (int oi = 0; oi < 4; oi++) {
            int r = mwarp * 32 + (oi >> 1) * 16 + (oi & 1) * 8 + g;
            float2 c = cmb[r];
            float2 res;
            res.x = o[oi].x + c.x + b20;
            res.y = o[oi].y + c.y + b21;
            ((float2*)out)[base + r] = res;
        }
    }
}

// ---------------- launch ----------------
extern "C" void kernel_launch(void* const* d_in, const int* in_sizes, int n_in,
                              void* d_out, int out_size) {
    const float* emb  = (const float*)d_in[0];
    const int*   idxg = (const int*)d_in[1];
    const int*   idxd = (const int*)d_in[2];
    const float* W1   = (const float*)d_in[3];
    const float* b1   = (const float*)d_in[4];
    const float* W2   = (const float*)d_in[5];
    const float* b2   = (const float*)d_in[6];
    float* out = (float*)d_out;

    static bool configured = false;
    if (!configured) {
        cudaFuncSetAttribute(fused_mlp_kernel,
                             cudaFuncAttributeMaxDynamicSharedMemorySize, SMEM_BYTES);
        configured = true;
    }

    prep_bfrag_kernel<<<128, 256>>>(W1);
    fused_mlp_kernel<<<2048, NTHREADS, SMEM_BYTES>>>(emb, idxg, idxd, b1, W2, b2, out);
}

// round 13
// speedup vs baseline: 2.7720x; 1.0490x over previous
// Fused gather+concat -> Linear(256,1024) -> GELU -> Linear(1024,2)
// sm_100 legacy mma.sync fp16 m16n8k16, 2 CTAs/SM.
// R12 resubmit (container infra flake; R5/R7/R10 precedent: identical source
// passed on retry).
// fp16 C-fragments (2 regs/tile vs 4) -> warp tile 32x64 at the same 32
// accumulator regs -> NGROUPS 16->8, A smem re-reads halved (LDS 4.5->3.5MB/CTA).
// B stream in K=32 blocks (8KB) through the same 3-slot single-barrier ring.
// Bias+GELU+W2 still fp32 in epilogue.

#include <cuda_runtime.h>
#include <cuda_fp16.h>
#include <cstdint>

#define NTHREADS   256
#define TILE_M     128
#define NGROUPS    8           // 1024 / 128
#define NKB        8           // K blocks per group-sweep: 8 x 32 = 256
#define NBLOCKS    64          // ngroups * nkb, linear B stream
#define BBLK_BYTES 8192        // 32 K x 128 cols x 2B

// smem layout (bytes)
#define OFF_IDX    0           // 256 ints
#define OFF_CMB    1024        // 128 float2
#define OFF_B1     2048        // 1024 f32
#define OFF_W2     6144        // 1024 float2
#define OFF_A      14336       // A frags: 16 ksteps x 8 mtiles x 32 lanes x 16B = 65536
#define OFF_B      79872       // 3 x 8KB B ring slots
#define SMEM_BYTES 104448

// ---------------- helpers ----------------
__device__ __forceinline__ uint32_t smem_u32(const void* p) {
    uint32_t a;
    asm("{ .reg .u64 t; cvta.to.shared.u64 t, %1; cvt.u32.u64 %0, t; }"
        : "=r"(a) : "l"(p));
    return a;
}

#define CP_ASYNC16(dst, src) \
    asm volatile("cp.async.cg.shared.global [%0], [%1], 16;" :: "r"(dst), "l"(src))
#define CP_COMMIT() asm volatile("cp.async.commit_group;" ::: "memory")
#define CP_WAIT(n)  asm volatile("cp.async.wait_group %0;" :: "n"(n) : "memory")

// pack two f32 -> f16x2 (lo = first arg), round-to-nearest
__device__ __forceinline__ uint32_t packh2(float lo, float hi) {
    uint32_t w;
    asm("cvt.rn.f16x2.f32 %0, %1, %2;" : "=r"(w) : "f"(hi), "f"(lo));
    return w;
}

// m16n8k16 with fp16 accumulators: C/D = 2 b32 regs (reg0 = row r cols 2c,2c+1;
// reg1 = row r+8), halving accumulator registers vs f32 C.
__device__ __forceinline__ void mma_f16c(uint32_t* c,
                                         uint32_t a0, uint32_t a1, uint32_t a2, uint32_t a3,
                                         uint32_t b0, uint32_t b1) {
    asm volatile("mma.sync.aligned.m16n8k16.row.col.f16.f16.f16.f16 "
                 "{%0,%1}, {%2,%3,%4,%5}, {%6,%7}, {%0,%1};"
                 : "+r"(c[0]), "+r"(c[1])
                 : "r"(a0), "r"(a1), "r"(a2), "r"(a3), "r"(b0), "r"(b1));
}

// GELU via tanh approximation + MUFU tanh (6 instrs)
__device__ __forceinline__ float gelu_fast(float x) {
    float t = x * x;
    float c = fmaf(t, 0.035677408136f, 0.7978845608028654f);
    float arg = x * c;
    float th;
    asm("tanh.approx.f32 %0, %1;" : "=f"(th) : "f"(arg));
    return x * fmaf(th, 0.5f, 0.5f);
}

// ---------------- W1 -> fp16 fragment-pair-order gmem (prep) ----------------
// Layout: [blk(64)][ks(2)][np(8)][lane(32)] uint4{b0_lo, b0_hi, b1_lo, b1_hi}
//   blk = ng*8 + kb ; k = kb*32 + ks*16 + (lane%4)*2 ; n = ng*128 + np*16 + lane/4
//   b0_lo = h2(W1[k][n],   W1[k+1][n])   b0_hi = h2(W1[k+8][n],   W1[k+9][n])
//   b1_lo = h2(W1[k][n+8], W1[k+1][n+8]) b1_hi = h2(W1[k+8][n+8], W1[k+9][n+8])
__device__ __align__(16) uint4 g_bfrag[32768];

__global__ void prep_bfrag_kernel(const float* __restrict__ W1) {
    int idx = blockIdx.x * blockDim.x + threadIdx.x;   // 0 .. 32767
    int lane = idx & 31;
    int np   = (idx >> 5) & 7;
    int ks   = (idx >> 8) & 1;
    int blk  = idx >> 9;                               // 0..63
    int ng = blk >> 3;
    int kb = blk & 7;
    int k = kb * 32 + ks * 16 + (lane & 3) * 2;
    int n = ng * 128 + np * 16 + (lane >> 2);
    uint4 v;
    v.x = packh2(W1[k * 1024 + n],           W1[(k + 1) * 1024 + n]);
    v.y = packh2(W1[(k + 8) * 1024 + n],     W1[(k + 9) * 1024 + n]);
    v.z = packh2(W1[k * 1024 + n + 8],       W1[(k + 1) * 1024 + n + 8]);
    v.w = packh2(W1[(k + 8) * 1024 + n + 8], W1[(k + 9) * 1024 + n + 8]);
    g_bfrag[idx] = v;
}

// ---------------- main fused kernel ----------------
__global__ void __launch_bounds__(NTHREADS, 2)
fused_mlp_kernel(const float* __restrict__ emb,
                 const int*   __restrict__ idxg,
                 const int*   __restrict__ idxd,
                 const float* __restrict__ b1,
                 const float* __restrict__ W2,
                 const float* __restrict__ b2,
                 float*       __restrict__ out) {
    extern __shared__ char smem[];
    const int tid   = threadIdx.x;
    const int wid   = tid >> 5;
    const int lane  = tid & 31;
    const int mwarp = wid & 3;        // 0..3 -> rows mwarp*32
    const int nwarp = wid >> 2;       // 0..1 -> cols nwarp*64 within group
    const int base  = blockIdx.x * TILE_M;

    // ---- stage idx / b1 / W2 ----
    if (tid < 128)      ((int*)(smem + OFF_IDX))[tid] = idxg[base + tid];
    else                ((int*)(smem + OFF_IDX))[tid] = idxd[base + tid - 128];
    for (int i = tid; i < 1024; i += NTHREADS)
        ((float*)(smem + OFF_B1))[i] = b1[i];
    for (int i = tid; i < 1024; i += NTHREADS)
        ((float2*)(smem + OFF_W2))[i] = ((const float2*)W2)[i];
    __syncthreads();

    // ---- gather A into fp16 fragment-order smem ----
    // [ks(16)][mt(8)][lane(32)] uint4 {a0,a1,a2,a3} (m16n8k16 A layout)
    {
        const int* idxs = (const int*)(smem + OFF_IDX);
        uint32_t* As32 = (uint32_t*)(smem + OFF_A);
        for (int i = tid; i < 8192; i += NTHREADS) {
            int m = i >> 6;
            int q = i & 63;
            int half_ = q >> 5;
            int c4    = q & 31;
            int node = idxs[half_ * 128 + m];
            float4 v = *(const float4*)(emb + (size_t)node * 128 + (size_t)c4 * 4);
            uint32_t w0 = packh2(v.x, v.y);    // cols (k, k+1)
            uint32_t w1 = packh2(v.z, v.w);    // cols (k+2, k+3)
            int kg  = half_ * 128 + c4 * 4;    // global K, multiple of 4
            int ks  = kg >> 4;                 // 0..15
            int kin = kg & 15;                 // 0,4,8,12
            int q0  = kin >> 1;                // pair index 0,2,4,6
            int clow = q0 & 3;                 // lane low bits for w0; w1 -> +1
            int slot = (((m & 15) >= 8) ? 1 : 0) + ((q0 >= 4) ? 2 : 0);
            int mt = m >> 4;
            int lane0 = (m & 7) * 4 + clow;
            uint32_t* dst = As32 + (((ks * 8 + mt) * 32 + lane0) << 2) + slot;
            dst[0] = w0;
            dst[4] = w1;                       // next lane, same slot
        }
    }

    // ---- preload B blocks 0 and 1 (two separate cp.async groups) ----
    const char* bsrc = (const char*)g_bfrag;
#pragma unroll
    for (int s = 0; s < 2; s++) {
        uint32_t dsts = smem_u32(smem + OFF_B + s * BBLK_BYTES);
        const char* srcs = bsrc + (size_t)s * BBLK_BYTES;
#pragma unroll
        for (int j = 0; j < 2; j++) {
            int L = tid + j * NTHREADS;                  // 0..511 x16B = 8KB
            CP_ASYNC16(dsts + L * 16, srcs + L * 16);
        }
        CP_COMMIT();
    }

    const float*  b1s = (const float*)(smem + OFF_B1);
    const float2* w2s = (const float2*)(smem + OFF_W2);
    float2 o[4];
    o[0] = make_float2(0.f, 0.f); o[1] = make_float2(0.f, 0.f);
    o[2] = make_float2(0.f, 0.f); o[3] = make_float2(0.f, 0.f);

    const uint4* Af = (const uint4*)(smem + OFF_A);
    int s_cur = 0;   // slot of current block (blk % 3)
    int s_pf  = 2;   // slot of block blk+2

    for (int ng = 0; ng < NGROUPS; ng++) {
        // fp16 accumulators: [mt][nt][reg] (reg0=row r, reg1=row r+8)
        uint32_t hacc[2][8][2];
#pragma unroll
        for (int mt = 0; mt < 2; mt++)
#pragma unroll
            for (int nt = 0; nt < 8; nt++) {
                hacc[mt][nt][0] = 0u;
                hacc[mt][nt][1] = 0u;
            }

        for (int kb = 0; kb < NKB; kb++) {
            int blk = ng * NKB + kb;
            // wait until block blk resident (in flight: blk, blk+1)
            if (blk + 1 < NBLOCKS) { CP_WAIT(1); } else { CP_WAIT(0); }
            __syncthreads();   // also fences reads of slot written by next prefetch
            // prefetch block blk+2 into slot (blk+2)%3 (read at iter blk-1, safe)
            if (blk + 2 < NBLOCKS) {
                uint32_t dstn = smem_u32(smem + OFF_B + s_pf * BBLK_BYTES);
                const char* srcn = bsrc + (size_t)(blk + 2) * BBLK_BYTES;
#pragma unroll
                for (int j = 0; j < 2; j++) {
                    int L = tid + j * NTHREADS;
                    CP_ASYNC16(dstn + L * 16, srcn + L * 16);
                }
                CP_COMMIT();
            }

            const uint4* Bf = (const uint4*)(smem + OFF_B + s_cur * BBLK_BYTES);
#pragma unroll
            for (int ks = 0; ks < 2; ks++) {
                int ksg = kb * 2 + ks;       // 0..15
                uint4 a0 = Af[(ksg * 8 + mwarp * 2 + 0) * 32 + lane];
                uint4 a1 = Af[(ksg * 8 + mwarp * 2 + 1) * 32 + lane];
#pragma unroll
                for (int p = 0; p < 4; p++) {
                    uint4 b = Bf[(ks * 8 + nwarp * 4 + p) * 32 + lane];
                    mma_f16c(hacc[0][2 * p + 0], a0.x, a0.y, a0.z, a0.w, b.x, b.y);
                    mma_f16c(hacc[0][2 * p + 1], a0.x, a0.y, a0.z, a0.w, b.z, b.w);
                    mma_f16c(hacc[1][2 * p + 0], a1.x, a1.y, a1.z, a1.w, b.x, b.y);
                    mma_f16c(hacc[1][2 * p + 1], a1.x, a1.y, a1.z, a1.w, b.z, b.w);
                }
            }
            // advance ring
            s_cur = (s_cur == 2) ? 0 : s_cur + 1;
            s_pf  = (s_pf  == 2) ? 0 : s_pf  + 1;
        }

        // ---- fused epilogue: unpack fp16 h, +b1 (f32), GELU, x W2 (f32) ----
        int jb = ng * 128 + nwarp * 64 + (lane & 3) * 2;
#pragma unroll
        for (int nt = 0; nt < 8; nt++) {
            int j = jb + nt * 8;
            float  bb0 = b1s[j],     bb1 = b1s[j + 1];
            float2 w0  = w2s[j];
            float2 w1  = w2s[j + 1];
#pragma unroll
            for (int mt = 0; mt < 2; mt++) {
#pragma unroll
                for (int sh = 0; sh < 2; sh++) {
                    int oi = mt * 2 + sh;
                    __half2 hp = *reinterpret_cast<__half2*>(&hacc[mt][nt][sh]);
                    float2 hf = __half22float2(hp);
                    float g0 = gelu_fast(hf.x + bb0);
                    float g1 = gelu_fast(hf.y + bb1);
                    o[oi].x = fmaf(g0, w0.x, o[oi].x);
                    o[oi].y = fmaf(g0, w0.y, o[oi].y);
                    o[oi].x = fmaf(g1, w1.x, o[oi].x);
                    o[oi].y = fmaf(g1, w1.y, o[oi].y);
                }
            }
        }
    }

    // ---- reduce within quads (lanes sharing a row) ----
#pragma unroll
    for (int oi = 0; oi < 4; oi++) {
        o[oi].x += __shfl_xor_sync(0xFFFFFFFFu, o[oi].x, 1);
        o[oi].x += __shfl_xor_sync(0xFFFFFFFFu, o[oi].x, 2);
        o[oi].y += __shfl_xor_sync(0xFFFFFFFFu, o[oi].y, 1);
        o[oi].y += __shfl_xor_sync(0xFFFFFFFFu, o[oi].y, 2);
    }

    // ---- combine the two n-warps, add b2, write out ----
    float2* cmb = (float2*)(smem + OFF_CMB);
    int g = lane >> 2;
    __syncthreads();
    if (nwarp == 1 && (lane & 3) == 0) {
#pragma unroll
        for (int oi = 0; oi < 4; oi++) {
            int r = mwarp * 32 + (oi >> 1) * 16 + (oi & 1) * 8 + g;
            cmb[r] = o[oi];
        }
    }
    __syncthreads();
    if (nwarp == 0 && (lane & 3) == 0) {
        float b20 = __ldg(&b2[0]);
        float b21 = __ldg(&b2[1]);
#pragma unroll
        for (int oi = 0; oi < 4; oi++) {
            int r = mwarp * 32 + (oi >> 1) * 16 + (oi & 1) * 8 + g;
            float2 c = cmb[r];
            float2 res;
            res.x = o[oi].x + c.x + b20;
            res.y = o[oi].y + c.y + b21;
            ((float2*)out)[base + r] = res;
        }
    }
}

// ---------------- launch ----------------
extern "C" void kernel_launch(void* const* d_in, const int* in_sizes, int n_in,
                              void* d_out, int out_size) {
    const float* emb  = (const float*)d_in[0];
    const int*   idxg = (const int*)d_in[1];
    const int*   idxd = (const int*)d_in[2];
    const float* W1   = (const float*)d_in[3];
    const float* b1   = (const float*)d_in[4];
    const float* W2   = (const float*)d_in[5];
    const float* b2   = (const float*)d_in[6];
    float* out = (float*)d_out;

    static bool configured = false;
    if (!configured) {
        cudaFuncSetAttribute(fused_mlp_kernel,
                             cudaFuncAttributeMaxDynamicSharedMemorySize, SMEM_BYTES);
        configured = true;
    }

    prep_bfrag_kernel<<<128, 256>>>(W1);
    fused_mlp_kernel<<<2048, NTHREADS, SMEM_BYTES>>>(emb, idxg, idxd, b1, W2, b2, out);
}